// round 15
// baseline (speedup 1.0000x reference)
#include <cuda_runtime.h>
#include <cuda_fp16.h>
#include <cstdint>

#define E_EXP 8
#define H_DIM 256
#define NHID  3
#define OMEGA 30.0f
#define NPTS  65536
#define TILE_M 64
#define NTHR  512
#define NMAT  (E_EXP * NHID)
#define NGRP  2                // expert groups per tile
#define EPG   (E_EXP / NGRP)   // experts per group

typedef unsigned long long u64;

// ---- SMEM layout (bytes) ----
#define S_A0    0              // A ping: 64 rows x 512B (XOR swizzled) fp16
#define S_A1    32768          // A pong (red aliases here in last layer)
#define S_WOUT  65536          // 256*4 floats (4KB)
#define S_W0S   69632          // 768 floats for layer0 W/b (4KB slot)
#define S_XS    73728          // 128 floats (1KB)
#define SMEM_BYTES 74752       // 73KB -> 2 CTAs/SM
// alias: red (64*8*3 floats = 6KB) over S_A1 (dead in last layer)

// W in MMA-fragment order: [mat][slice(8)][chunk(8)][h(2)][nt(4)][lane(32)] x u64
__device__ u64 g_Wf[NMAT * 16384];

static __device__ __forceinline__ uint32_t smem_u32(const void* p) {
    uint32_t a;
    asm("{ .reg .u64 t; cvta.to.shared.u64 t, %1; cvt.u32.u64 %0, t; }" : "=r"(a) : "l"(p));
    return a;
}

// A swizzle: row m (0..63) x 32 16B-units; unit low-3 bits XOR row low-3 bits
static __device__ __forceinline__ uint32_t a_sw(uint32_t m, uint32_t u) {
    return m * 512u + ((((u ^ m) & 7u) | (u & 24u)) << 4);
}

#define LDSM4(r0, r1, r2, r3, addr) \
    asm volatile("ldmatrix.sync.aligned.m8n8.x4.shared.b16 {%0,%1,%2,%3}, [%4];" \
                 : "=r"(r0), "=r"(r1), "=r"(r2), "=r"(r3) : "r"(addr))

static __device__ __forceinline__ void mma16816(float* c, const uint32_t* a,
                                                uint32_t b0, uint32_t b1) {
    asm volatile("mma.sync.aligned.m16n8k16.row.col.f32.f16.f16.f32 "
                 "{%0,%1,%2,%3}, {%4,%5,%6,%7}, {%8,%9}, {%0,%1,%2,%3};"
                 : "+f"(c[0]), "+f"(c[1]), "+f"(c[2]), "+f"(c[3])
                 : "r"(a[0]), "r"(a[1]), "r"(a[2]), "r"(a[3]), "r"(b0), "r"(b1));
}

// MUFU-based sin
static __device__ __forceinline__ float fast_sin(float a) {
    return __sinf(a);
}

// ---------------- prep: pack W into MMA-fragment order ----------------
__global__ void prep_frag_kernel(const float* __restrict__ Wh) {
    const int t   = blockIdx.x * 256 + threadIdx.x;   // 0..16383 within mat
    const int mat = blockIdx.y;
    const int lane = t & 31;
    const int nt   = (t >> 5) & 3;
    const int h    = (t >> 7) & 1;
    const int c    = (t >> 8) & 7;
    const int sl   = t >> 11;
    const int n = sl * 32 + nt * 8 + (lane >> 2);
    const int k = c * 32 + h * 16 + (lane & 3) * 2;
    const float* src = Wh + (size_t)mat * 65536;      // [k][n]
    unsigned short a0 = __half_as_ushort(__float2half_rn(src[(k + 0) * 256 + n]));
    unsigned short a1 = __half_as_ushort(__float2half_rn(src[(k + 1) * 256 + n]));
    unsigned short a8 = __half_as_ushort(__float2half_rn(src[(k + 8) * 256 + n]));
    unsigned short a9 = __half_as_ushort(__float2half_rn(src[(k + 9) * 256 + n]));
    uint32_t b0 = (uint32_t)a0 | ((uint32_t)a1 << 16);
    uint32_t b1 = (uint32_t)a8 | ((uint32_t)a9 << 16);
    g_Wf[(size_t)mat * 16384 + t] = (u64)b0 | ((u64)b1 << 32);
}

__global__ void zero_out_kernel(float* __restrict__ out) {
    int i = blockIdx.x * 256 + threadIdx.x;
    if (i < NPTS * 3) out[i] = 0.f;
}

// ---------------- main kernel ----------------
extern __shared__ char smem[];

__global__ void __launch_bounds__(NTHR, 2)
moe_mma_kernel(const float* __restrict__ x,
               const float* __restrict__ gate_W,
               const float* __restrict__ gate_b,
               const float* __restrict__ W0,
               const float* __restrict__ b0,
               const float* __restrict__ Wh_unused,
               const float* __restrict__ bh,
               const float* __restrict__ Wout,
               const float* __restrict__ bout,
               float* __restrict__ out)
{
    const uint32_t smem0 = smem_u32(smem);
    char*  sc     = smem;
    float* wout_s = (float*)(sc + S_WOUT);
    float* w0s    = (float*)(sc + S_W0S);
    float* xs     = (float*)(sc + S_XS);
    float* red    = (float*)(sc + S_A1);     // alias (A1 dead in last layer)

    const int tile = blockIdx.x >> 1;        // point tile
    const int e0   = (blockIdx.x & 1) * EPG; // expert group start

    const int tid    = threadIdx.x;
    const int lane   = tid & 31;
    const int wid    = tid >> 5;             // 0..15
    const int warp_m = wid & 1;              // M half
    const int warp_n = wid >> 1;             // 0..7: n-slice [warp_n*32, +32)
    const int nw     = warp_n * 32;
    const int m0l    = warp_m * 32 + (lane & 15);   // A ldmatrix row base

    if (tid < 128) xs[tid] = x[tile * 128 + tid];
    __syncthreads();

    // gate softmax (threads < 64 own one point) — all 8 logits for normalization
    float gts[EPG];
    float cb0 = 0.f, cb1 = 0.f, cb2 = 0.f;
    if (tid < TILE_M) {
        float x0 = xs[tid * 2], x1 = xs[tid * 2 + 1];
        float lg[E_EXP];
        float mx = -1e30f;
        #pragma unroll
        for (int e = 0; e < E_EXP; e++) {
            float v = fmaf(x0, __ldg(gate_W + e), fmaf(x1, __ldg(gate_W + 8 + e), __ldg(gate_b + e)));
            lg[e] = v; mx = fmaxf(mx, v);
        }
        float s = 0.f;
        #pragma unroll
        for (int e = 0; e < E_EXP; e++) { lg[e] = expf(lg[e] - mx); s += lg[e]; }
        float inv = 1.0f / s;
        #pragma unroll
        for (int q = 0; q < EPG; q++) gts[q] = lg[e0 + q] * inv;
    }

    #pragma unroll 1
    for (int eq = 0; eq < EPG; eq++) {
        const int e = e0 + eq;
        // stage Wout[e] -> [256][4]; W0/b0 -> w0s[768]
        if (tid < 256) {
            wout_s[tid * 4 + 0] = __ldg(Wout + e * 768 + tid * 3 + 0);
            wout_s[tid * 4 + 1] = __ldg(Wout + e * 768 + tid * 3 + 1);
            wout_s[tid * 4 + 2] = __ldg(Wout + e * 768 + tid * 3 + 2);
            wout_s[tid * 4 + 3] = 0.f;
        }
        for (int i = tid; i < 768; i += NTHR)
            w0s[i] = (i < 512) ? __ldg(W0 + e * 512 + i) : __ldg(b0 + e * 256 + (i - 512));
        __syncthreads();

        // -------- layer 0 (K=2, fp32) -> A (fp16) into A0 --------
        {
            const int m = tid >> 3, p = tid & 7;   // 8 threads per row
            const float x0 = xs[m * 2], x1 = xs[m * 2 + 1];
            #pragma unroll 4
            for (int j = 0; j < 16; j++) {
                int c0 = j * 16 + p * 2;
                float z0 = fmaf(x0, w0s[c0],     fmaf(x1, w0s[256 + c0],     w0s[512 + c0]));
                float z1 = fmaf(x0, w0s[c0 + 1], fmaf(x1, w0s[256 + c0 + 1], w0s[512 + c0 + 1]));
                float s0 = fast_sin(OMEGA * z0);
                float s1 = fast_sin(OMEGA * z1);
                __half2 h = __floats2half2_rn(s0, s1);
                uint32_t off = a_sw((uint32_t)m, (uint32_t)(c0 >> 3)) + (p & 3) * 4;
                *(uint32_t*)(sc + S_A0 + off) = *(uint32_t*)&h;
            }
            __syncthreads();
        }

        // -------- hidden layers; A ping-pongs: l0 A0->A1, l1 A1->A0, l2 A0->red --------
        uint32_t aoff = 0;   // read offset for this layer
        #pragma unroll 1
        for (int l = 0; l < NHID; l++) {
            const float* bbg = bh + (e * 3 + l) * 256;
            const u64* wf = g_Wf + (size_t)(e * 3 + l) * 16384 + (warp_n << 11) + lane;

            float cacc[2][4][4];
            #pragma unroll
            for (int mt = 0; mt < 2; mt++)
                #pragma unroll
                for (int nt = 0; nt < 4; nt++)
                    #pragma unroll
                    for (int q = 0; q < 4; q++) cacc[mt][nt][q] = 0.f;

            // -------- register-direct W fragments, one h-step lookahead --------
            uint2 wb2[2][4];
            #pragma unroll
            for (int q = 0; q < 4; q++)
                wb2[0][q] = __ldg((const uint2*)(wf + q * 32));   // (c0,h0)

            #pragma unroll 2
            for (int c = 0; c < 8; c++) {
                #pragma unroll
                for (int h = 0; h < 2; h++) {
                    const int p = (c * 2 + h) & 1;
                    // prefetch next h-step: (c,1) or (c+1,0)
                    if (!(c == 7 && h == 1)) {
                        const int nc = (h == 0) ? c : c + 1;
                        const int nh = h ^ 1;
                        const u64* wn = wf + nc * 256 + nh * 128;
                        #pragma unroll
                        for (int q = 0; q < 4; q++)
                            wb2[p ^ 1][q] = __ldg((const uint2*)(wn + q * 32));
                    }
                    // A fragments for this k16 (2 m-tiles in our M half)
                    const uint32_t ubase = (uint32_t)(c * 4 + h * 2) + (uint32_t)(lane >> 4);
                    uint32_t af[2][4];
                    #pragma unroll
                    for (int mt = 0; mt < 2; mt++) {
                        uint32_t aa = smem0 + S_A0 + aoff + a_sw((uint32_t)(mt * 16 + m0l), ubase);
                        LDSM4(af[mt][0], af[mt][1], af[mt][2], af[mt][3], aa);
                    }
                    #pragma unroll
                    for (int mt = 0; mt < 2; mt++)
                        #pragma unroll
                        for (int nt = 0; nt < 4; nt++)
                            mma16816(cacc[mt][nt], af[mt], wb2[p][nt].x, wb2[p][nt].y);
                }
            }

            // epilogue writes the OTHER A buffer (or red); bias via L2 __ldg
            if (l < NHID - 1) {
                const uint32_t dst = (uint32_t)S_A0 + (aoff ^ 32768u);
                #pragma unroll
                for (int mt = 0; mt < 2; mt++) {
                    int r0 = warp_m * 32 + mt * 16 + (lane >> 2);
                    #pragma unroll
                    for (int nt = 0; nt < 4; nt++) {
                        int n0 = nw + nt * 8 + 2 * (lane & 3);
                        uint32_t u = (uint32_t)(n0 >> 3);
                        float2 bb = *(const float2*)(bbg + n0);
                        float* cc = cacc[mt][nt];
                        float s00 = fast_sin(OMEGA * (cc[0] + bb.x));
                        float s01 = fast_sin(OMEGA * (cc[1] + bb.y));
                        float s10 = fast_sin(OMEGA * (cc[2] + bb.x));
                        float s11 = fast_sin(OMEGA * (cc[3] + bb.y));
                        __half2 h0 = __floats2half2_rn(s00, s01);
                        __half2 h1 = __floats2half2_rn(s10, s11);
                        uint32_t o0 = a_sw((uint32_t)r0, u) + (lane & 3) * 4;
                        uint32_t o1 = a_sw((uint32_t)(r0 + 8), u) + (lane & 3) * 4;
                        *(uint32_t*)(sc + dst + o0) = *(uint32_t*)&h0;
                        *(uint32_t*)(sc + dst + o1) = *(uint32_t*)&h1;
                    }
                }
                aoff ^= 32768u;
                __syncthreads();   // next layer's A complete
            } else {
                // last layer: bias + sin + Wout dot + reduce + gated combine
                float o[4][3];
                #pragma unroll
                for (int i = 0; i < 4; i++)
                    #pragma unroll
                    for (int c3 = 0; c3 < 3; c3++) o[i][c3] = 0.f;
                #pragma unroll
                for (int mt = 0; mt < 2; mt++) {
                    #pragma unroll
                    for (int nt = 0; nt < 4; nt++) {
                        int n0 = nw + nt * 8 + 2 * (lane & 3);
                        float2 bb = *(const float2*)(bbg + n0);
                        float* cc = cacc[mt][nt];
                        float s00 = fast_sin(OMEGA * (cc[0] + bb.x));
                        float s01 = fast_sin(OMEGA * (cc[1] + bb.y));
                        float s10 = fast_sin(OMEGA * (cc[2] + bb.x));
                        float s11 = fast_sin(OMEGA * (cc[3] + bb.y));
                        const float* wA = wout_s + n0 * 4;
                        const float* wB = wout_s + (n0 + 1) * 4;
                        #pragma unroll
                        for (int c3 = 0; c3 < 3; c3++) {
                            o[mt * 2 + 0][c3] = fmaf(s00, wA[c3], fmaf(s01, wB[c3], o[mt * 2 + 0][c3]));
                            o[mt * 2 + 1][c3] = fmaf(s10, wA[c3], fmaf(s11, wB[c3], o[mt * 2 + 1][c3]));
                        }
                    }
                }
                #pragma unroll
                for (int i = 0; i < 4; i++)
                    #pragma unroll
                    for (int c3 = 0; c3 < 3; c3++) {
                        float v = o[i][c3];
                        v += __shfl_xor_sync(0xFFFFFFFF, v, 1);
                        v += __shfl_xor_sync(0xFFFFFFFF, v, 2);
                        o[i][c3] = v;
                    }
                if ((lane & 3) == 0) {
                    int q = lane >> 2;
                    #pragma unroll
                    for (int mt = 0; mt < 2; mt++)
                        #pragma unroll
                        for (int i = 0; i < 2; i++) {
                            int r = warp_m * 32 + mt * 16 + i * 8 + q;
                            #pragma unroll
                            for (int c3 = 0; c3 < 3; c3++)
                                red[r * 24 + warp_n * 3 + c3] = o[mt * 2 + i][c3];
                        }
                }
                __syncthreads();   // all red written; all warps past K-loop
                if (tid < TILE_M) {
                    float g = gts[eq];
                    #pragma unroll
                    for (int c3 = 0; c3 < 3; c3++) {
                        float oc = __ldg(bout + e * 3 + c3);
                        #pragma unroll
                        for (int w = 0; w < 8; w++)
                            oc += red[tid * 24 + w * 3 + c3];
                        if (c3 == 0) cb0 = fmaf(g, oc, cb0);
                        else if (c3 == 1) cb1 = fmaf(g, oc, cb1);
                        else cb2 = fmaf(g, oc, cb2);
                    }
                }
                __syncthreads();   // red consumed before next expert's layer 0
            }
        }
    }

    if (tid < TILE_M) {
        int r = tile * TILE_M + tid;
        atomicAdd(&out[r * 3 + 0], cb0);
        atomicAdd(&out[r * 3 + 1], cb1);
        atomicAdd(&out[r * 3 + 2], cb2);
    }
}

extern "C" void kernel_launch(void* const* d_in, const int* in_sizes, int n_in,
                              void* d_out, int out_size) {
    (void)in_sizes; (void)n_in; (void)out_size;
    const float* x      = (const float*)d_in[0];
    const float* gate_W = (const float*)d_in[1];
    const float* gate_b = (const float*)d_in[2];
    const float* W0     = (const float*)d_in[3];
    const float* b0     = (const float*)d_in[4];
    const float* Wh     = (const float*)d_in[5];
    const float* bh     = (const float*)d_in[6];
    const float* Wout   = (const float*)d_in[7];
    const float* bout   = (const float*)d_in[8];
    float* out = (float*)d_out;

    dim3 pg(64, NMAT);
    prep_frag_kernel<<<pg, 256>>>(Wh);
    zero_out_kernel<<<(NPTS * 3 + 255) / 256, 256>>>(out);

    cudaFuncSetAttribute(moe_mma_kernel,
                         cudaFuncAttributeMaxDynamicSharedMemorySize, SMEM_BYTES);
    moe_mma_kernel<<<(NPTS / TILE_M) * NGRP, NTHR, SMEM_BYTES>>>(
        x, gate_W, gate_b, W0, b0, Wh, bh, Wout, bout, out);
}

// round 16
// speedup vs baseline: 1.0646x; 1.0646x over previous
#include <cuda_runtime.h>
#include <cuda_fp16.h>
#include <cstdint>

#define E_EXP 8
#define H_DIM 256
#define NHID  3
#define OMEGA 30.0f
#define NPTS  65536
#define TILE_M 64
#define NTHR  256
#define NMAT  (E_EXP * NHID)
#define NGRP  2                // expert groups per tile
#define EPG   (E_EXP / NGRP)   // experts per group

typedef unsigned long long u64;

// ---- SMEM layout (bytes) ----
#define S_A0    0              // A ping: 64 rows x 512B (XOR swizzled) fp16
#define S_A1    32768          // A pong (red aliases here in last layer)
#define S_WOUT  65536          // 256*4 floats (4KB)
#define S_W0S   69632          // 768 floats for layer0 W/b (4KB slot)
#define S_XS    73728          // 128 floats (1KB)
#define SMEM_BYTES 74752       // 73KB -> 2 CTAs/SM
// alias: red (64*24 floats = 6KB) over S_A1 (dead in last layer)

// W in MMA-fragment order, per-lane contiguous:
// [mat][slice(8)][chunk(8)][lane(32)][q(8)] x u64, q = h*4 + nt
// u64 = {b0: halfs W[k0][n], W[k0+1][n]} | {b1: halfs W[k0+8][n], W[k0+9][n]} << 32
__device__ u64 g_Wf[NMAT * 16384];

static __device__ __forceinline__ uint32_t smem_u32(const void* p) {
    uint32_t a;
    asm("{ .reg .u64 t; cvta.to.shared.u64 t, %1; cvt.u32.u64 %0, t; }" : "=r"(a) : "l"(p));
    return a;
}

// A swizzle: row m (0..63) x 32 16B-units; unit low-3 bits XOR row low-3 bits
static __device__ __forceinline__ uint32_t a_sw(uint32_t m, uint32_t u) {
    return m * 512u + ((((u ^ m) & 7u) | (u & 24u)) << 4);
}

#define LDSM4(r0, r1, r2, r3, addr) \
    asm volatile("ldmatrix.sync.aligned.m8n8.x4.shared.b16 {%0,%1,%2,%3}, [%4];" \
                 : "=r"(r0), "=r"(r1), "=r"(r2), "=r"(r3) : "r"(addr))

static __device__ __forceinline__ void mma16816(float* c, const uint32_t* a,
                                                uint32_t b0, uint32_t b1) {
    asm volatile("mma.sync.aligned.m16n8k16.row.col.f32.f16.f16.f32 "
                 "{%0,%1,%2,%3}, {%4,%5,%6,%7}, {%8,%9}, {%0,%1,%2,%3};"
                 : "+f"(c[0]), "+f"(c[1]), "+f"(c[2]), "+f"(c[3])
                 : "r"(a[0]), "r"(a[1]), "r"(a[2]), "r"(a[3]), "r"(b0), "r"(b1));
}

// MUFU-based sin
static __device__ __forceinline__ float fast_sin(float a) {
    return __sinf(a);
}

// ---------------- prep: pack W into MMA-fragment order (lane-contiguous) ----------------
__global__ void prep_frag_kernel(const float* __restrict__ Wh) {
    const int t   = blockIdx.x * 256 + threadIdx.x;   // 0..16383 within mat
    const int mat = blockIdx.y;
    const int q    = t & 7;          // h*4 + nt
    const int lane = (t >> 3) & 31;
    const int c    = (t >> 8) & 7;
    const int sl   = t >> 11;
    const int nt   = q & 3;
    const int h    = (q >> 2) & 1;
    const int n = sl * 32 + nt * 8 + (lane >> 2);
    const int k = c * 32 + h * 16 + (lane & 3) * 2;
    const float* src = Wh + (size_t)mat * 65536;      // [k][n]
    unsigned short a0 = __half_as_ushort(__float2half_rn(src[(k + 0) * 256 + n]));
    unsigned short a1 = __half_as_ushort(__float2half_rn(src[(k + 1) * 256 + n]));
    unsigned short a8 = __half_as_ushort(__float2half_rn(src[(k + 8) * 256 + n]));
    unsigned short a9 = __half_as_ushort(__float2half_rn(src[(k + 9) * 256 + n]));
    uint32_t b0 = (uint32_t)a0 | ((uint32_t)a1 << 16);
    uint32_t b1 = (uint32_t)a8 | ((uint32_t)a9 << 16);
    g_Wf[(size_t)mat * 16384 + t] = (u64)b0 | ((u64)b1 << 32);
}

__global__ void zero_out_kernel(float* __restrict__ out) {
    int i = blockIdx.x * 256 + threadIdx.x;
    if (i < NPTS * 3) out[i] = 0.f;
}

// ---------------- main kernel ----------------
extern __shared__ char smem[];

__global__ void __launch_bounds__(NTHR, 2)
moe_mma_kernel(const float* __restrict__ x,
               const float* __restrict__ gate_W,
               const float* __restrict__ gate_b,
               const float* __restrict__ W0,
               const float* __restrict__ b0,
               const float* __restrict__ Wh_unused,
               const float* __restrict__ bh,
               const float* __restrict__ Wout,
               const float* __restrict__ bout,
               float* __restrict__ out)
{
    const uint32_t smem0 = smem_u32(smem);
    char*  sc     = smem;
    float* wout_s = (float*)(sc + S_WOUT);
    float* w0s    = (float*)(sc + S_W0S);
    float* xs     = (float*)(sc + S_XS);
    float* red    = (float*)(sc + S_A1);     // alias (A1 dead in last layer)

    const int tile = blockIdx.x >> 1;        // point tile
    const int e0   = (blockIdx.x & 1) * EPG; // expert group start

    const int tid  = threadIdx.x;
    const int lane = tid & 31;
    const int wid  = tid >> 5;               // warp owns n-slice [wid*32, wid*32+32)
    const int nw   = wid * 32;
    const int m0l  = lane & 15;              // A ldmatrix row base

    if (tid < 128) xs[tid] = x[tile * 128 + tid];
    __syncthreads();

    // gate softmax (threads < 64 own one point) — all 8 logits for normalization
    float gts[EPG];
    float cb0 = 0.f, cb1 = 0.f, cb2 = 0.f;
    if (tid < TILE_M) {
        float x0 = xs[tid * 2], x1 = xs[tid * 2 + 1];
        float lg[E_EXP];
        float mx = -1e30f;
        #pragma unroll
        for (int e = 0; e < E_EXP; e++) {
            float v = fmaf(x0, __ldg(gate_W + e), fmaf(x1, __ldg(gate_W + 8 + e), __ldg(gate_b + e)));
            lg[e] = v; mx = fmaxf(mx, v);
        }
        float s = 0.f;
        #pragma unroll
        for (int e = 0; e < E_EXP; e++) { lg[e] = expf(lg[e] - mx); s += lg[e]; }
        float inv = 1.0f / s;
        #pragma unroll
        for (int q = 0; q < EPG; q++) gts[q] = lg[e0 + q] * inv;
    }

    #pragma unroll 1
    for (int eq = 0; eq < EPG; eq++) {
        const int e = e0 + eq;
        // stage Wout[e] -> [256][4]; W0/b0 -> w0s[768]
        wout_s[tid * 4 + 0] = __ldg(Wout + e * 768 + tid * 3 + 0);
        wout_s[tid * 4 + 1] = __ldg(Wout + e * 768 + tid * 3 + 1);
        wout_s[tid * 4 + 2] = __ldg(Wout + e * 768 + tid * 3 + 2);
        wout_s[tid * 4 + 3] = 0.f;
        for (int i = tid; i < 768; i += NTHR)
            w0s[i] = (i < 512) ? __ldg(W0 + e * 512 + i) : __ldg(b0 + e * 256 + (i - 512));
        __syncthreads();

        // -------- layer 0 (K=2, fp32) -> A (fp16) into A0 --------
        {
            const int m = tid >> 2, p = tid & 3;
            const float x0 = xs[m * 2], x1 = xs[m * 2 + 1];
            #pragma unroll 4
            for (int j = 0; j < 32; j++) {
                int c0 = j * 8 + p * 2;
                float z0 = fmaf(x0, w0s[c0],     fmaf(x1, w0s[256 + c0],     w0s[512 + c0]));
                float z1 = fmaf(x0, w0s[c0 + 1], fmaf(x1, w0s[256 + c0 + 1], w0s[512 + c0 + 1]));
                float s0 = fast_sin(OMEGA * z0);
                float s1 = fast_sin(OMEGA * z1);
                __half2 h = __floats2half2_rn(s0, s1);
                uint32_t off = a_sw(m, j) + p * 4;
                *(uint32_t*)(sc + S_A0 + off) = *(uint32_t*)&h;
            }
            __syncthreads();
        }

        // -------- hidden layers; A ping-pongs: l0 A0->A1, l1 A1->A0, l2 A0->red --------
        uint32_t aoff = 0;   // read offset for this layer
        #pragma unroll 1
        for (int l = 0; l < NHID; l++) {
            const float* bbg = bh + (e * 3 + l) * 256;
            const u64* wf = g_Wf + (size_t)(e * 3 + l) * 16384 + (wid << 11) + lane * 8;

            float cacc[4][4][4];
            #pragma unroll
            for (int mt = 0; mt < 4; mt++)
                #pragma unroll
                for (int nt = 0; nt < 4; nt++)
                    #pragma unroll
                    for (int q = 0; q < 4; q++) cacc[mt][nt][q] = 0.f;

            // -------- register-direct W fragments (4x LDG.128/chunk), 1-chunk lookahead --------
            uint4 bfr[2][4];   // [buf][pair]: pair p holds fragments q=2p (x,y) and q=2p+1 (z,w)
            #pragma unroll
            for (int p = 0; p < 4; p++)
                bfr[0][p] = __ldg((const uint4*)(wf + p * 2));

            #pragma unroll
            for (int c = 0; c < 8; c++) {
                const int cur = c & 1;
                if (c < 7) {
                    const u64* wn = wf + (c + 1) * 256;
                    #pragma unroll
                    for (int p = 0; p < 4; p++)
                        bfr[cur ^ 1][p] = __ldg((const uint4*)(wn + p * 2));
                }
                #pragma unroll
                for (int h = 0; h < 2; h++) {
                    const uint32_t ubase = (uint32_t)(c * 4 + h * 2) + (uint32_t)(lane >> 4);
                    uint32_t af[4][4];
                    #pragma unroll
                    for (int mt = 0; mt < 4; mt++) {
                        uint32_t aa = smem0 + S_A0 + aoff + a_sw((uint32_t)(mt * 16 + m0l), ubase);
                        LDSM4(af[mt][0], af[mt][1], af[mt][2], af[mt][3], aa);
                    }
                    // fragments q = h*4 + nt: pairs p = h*2 + (nt>>1); even nt -> (x,y), odd -> (z,w)
                    const uint4 pa = bfr[cur][h * 2 + 0];
                    const uint4 pb = bfr[cur][h * 2 + 1];
                    #pragma unroll
                    for (int mt = 0; mt < 4; mt++) {
                        mma16816(cacc[mt][0], af[mt], pa.x, pa.y);
                        mma16816(cacc[mt][1], af[mt], pa.z, pa.w);
                        mma16816(cacc[mt][2], af[mt], pb.x, pb.y);
                        mma16816(cacc[mt][3], af[mt], pb.z, pb.w);
                    }
                }
            }

            // epilogue writes the OTHER A buffer (or red); bias via L2 __ldg
            if (l < NHID - 1) {
                const uint32_t dst = (uint32_t)S_A0 + (aoff ^ 32768u);
                #pragma unroll
                for (int mt = 0; mt < 4; mt++) {
                    int r0 = mt * 16 + (lane >> 2);
                    #pragma unroll
                    for (int nt = 0; nt < 4; nt++) {
                        int n0 = nw + nt * 8 + 2 * (lane & 3);
                        uint32_t u = (uint32_t)(n0 >> 3);
                        float2 bb = *(const float2*)(bbg + n0);
                        float* cc = cacc[mt][nt];
                        float s00 = fast_sin(OMEGA * (cc[0] + bb.x));
                        float s01 = fast_sin(OMEGA * (cc[1] + bb.y));
                        float s10 = fast_sin(OMEGA * (cc[2] + bb.x));
                        float s11 = fast_sin(OMEGA * (cc[3] + bb.y));
                        __half2 h0 = __floats2half2_rn(s00, s01);
                        __half2 h1 = __floats2half2_rn(s10, s11);
                        uint32_t o0 = a_sw((uint32_t)r0, u) + (lane & 3) * 4;
                        uint32_t o1 = a_sw((uint32_t)(r0 + 8), u) + (lane & 3) * 4;
                        *(uint32_t*)(sc + dst + o0) = *(uint32_t*)&h0;
                        *(uint32_t*)(sc + dst + o1) = *(uint32_t*)&h1;
                    }
                }
                aoff ^= 32768u;
                __syncthreads();   // next layer's A complete
            } else {
                // last layer: bias + sin + Wout dot + reduce + gated combine
                float o[8][3];
                #pragma unroll
                for (int i = 0; i < 8; i++)
                    #pragma unroll
                    for (int c3 = 0; c3 < 3; c3++) o[i][c3] = 0.f;
                #pragma unroll
                for (int mt = 0; mt < 4; mt++) {
                    #pragma unroll
                    for (int nt = 0; nt < 4; nt++) {
                        int n0 = nw + nt * 8 + 2 * (lane & 3);
                        float2 bb = *(const float2*)(bbg + n0);
                        float* cc = cacc[mt][nt];
                        float s00 = fast_sin(OMEGA * (cc[0] + bb.x));
                        float s01 = fast_sin(OMEGA * (cc[1] + bb.y));
                        float s10 = fast_sin(OMEGA * (cc[2] + bb.x));
                        float s11 = fast_sin(OMEGA * (cc[3] + bb.y));
                        const float* wA = wout_s + n0 * 4;
                        const float* wB = wout_s + (n0 + 1) * 4;
                        #pragma unroll
                        for (int c3 = 0; c3 < 3; c3++) {
                            o[mt * 2 + 0][c3] = fmaf(s00, wA[c3], fmaf(s01, wB[c3], o[mt * 2 + 0][c3]));
                            o[mt * 2 + 1][c3] = fmaf(s10, wA[c3], fmaf(s11, wB[c3], o[mt * 2 + 1][c3]));
                        }
                    }
                }
                #pragma unroll
                for (int i = 0; i < 8; i++)
                    #pragma unroll
                    for (int c3 = 0; c3 < 3; c3++) {
                        float v = o[i][c3];
                        v += __shfl_xor_sync(0xFFFFFFFF, v, 1);
                        v += __shfl_xor_sync(0xFFFFFFFF, v, 2);
                        o[i][c3] = v;
                    }
                if ((lane & 3) == 0) {
                    int q = lane >> 2;
                    #pragma unroll
                    for (int mt = 0; mt < 4; mt++)
                        #pragma unroll
                        for (int i = 0; i < 2; i++) {
                            int r = mt * 16 + i * 8 + q;
                            #pragma unroll
                            for (int c3 = 0; c3 < 3; c3++)
                                red[r * 24 + wid * 3 + c3] = o[mt * 2 + i][c3];
                        }
                }
                __syncthreads();   // all red written; all warps past K-loop
                if (tid < TILE_M) {
                    float g = gts[eq];
                    #pragma unroll
                    for (int c3 = 0; c3 < 3; c3++) {
                        float oc = __ldg(bout + e * 3 + c3);
                        #pragma unroll
                        for (int w = 0; w < 8; w++)
                            oc += red[tid * 24 + w * 3 + c3];
                        if (c3 == 0) cb0 = fmaf(g, oc, cb0);
                        else if (c3 == 1) cb1 = fmaf(g, oc, cb1);
                        else cb2 = fmaf(g, oc, cb2);
                    }
                }
                __syncthreads();   // red consumed before next expert's layer 0
            }
        }
    }

    if (tid < TILE_M) {
        int r = tile * TILE_M + tid;
        atomicAdd(&out[r * 3 + 0], cb0);
        atomicAdd(&out[r * 3 + 1], cb1);
        atomicAdd(&out[r * 3 + 2], cb2);
    }
}

extern "C" void kernel_launch(void* const* d_in, const int* in_sizes, int n_in,
                              void* d_out, int out_size) {
    (void)in_sizes; (void)n_in; (void)out_size;
    const float* x      = (const float*)d_in[0];
    const float* gate_W = (const float*)d_in[1];
    const float* gate_b = (const float*)d_in[2];
    const float* W0     = (const float*)d_in[3];
    const float* b0     = (const float*)d_in[4];
    const float* Wh     = (const float*)d_in[5];
    const float* bh     = (const float*)d_in[6];
    const float* Wout   = (const float*)d_in[7];
    const float* bout   = (const float*)d_in[8];
    float* out = (float*)d_out;

    dim3 pg(64, NMAT);
    prep_frag_kernel<<<pg, 256>>>(Wh);
    zero_out_kernel<<<(NPTS * 3 + 255) / 256, 256>>>(out);

    cudaFuncSetAttribute(moe_mma_kernel,
                         cudaFuncAttributeMaxDynamicSharedMemorySize, SMEM_BYTES);
    moe_mma_kernel<<<(NPTS / TILE_M) * NGRP, NTHR, SMEM_BYTES>>>(
        x, gate_W, gate_b, W0, b0, Wh, bh, Wout, bout, out);
}

// round 17
// speedup vs baseline: 1.3897x; 1.3054x over previous
#include <cuda_runtime.h>
#include <cuda_fp16.h>
#include <cstdint>

#define E_EXP 8
#define H_DIM 256
#define NHID  3
#define OMEGA 30.0f
#define NPTS  65536
#define TILE_M 64
#define NTHR  256
#define NMAT  (E_EXP * NHID)
#define NGRP  2                // expert groups per tile
#define EPG   (E_EXP / NGRP)   // experts per group

typedef unsigned long long u64;

// ---- SMEM layout (bytes) ----
#define S_A0    0              // A ping: 64 rows x 512B (XOR swizzled) fp16
#define S_A1    32768          // A pong (red aliases here in last layer)
#define S_WOUT  65536          // 256*4 floats (4KB)
#define S_W0S   69632          // 768 floats for layer0 W/b (4KB slot)
#define S_XS    73728          // 128 floats (1KB)
#define SMEM_BYTES 74752       // 73KB -> 2 CTAs/SM
// alias: red (64*24 floats = 6KB) over S_A1 (dead in last layer)

// W in MMA-fragment order: [mat][slice(8)][chunk(8)][h(2)][nt(4)][lane(32)] x u64
// u64 = {b0: halfs W[k0][n], W[k0+1][n]} | {b1: halfs W[k0+8][n], W[k0+9][n]} << 32
__device__ u64 g_Wf[NMAT * 16384];

static __device__ __forceinline__ uint32_t smem_u32(const void* p) {
    uint32_t a;
    asm("{ .reg .u64 t; cvta.to.shared.u64 t, %1; cvt.u32.u64 %0, t; }" : "=r"(a) : "l"(p));
    return a;
}

// A swizzle: row m (0..63) x 32 16B-units; unit low-3 bits XOR row low-3 bits
static __device__ __forceinline__ uint32_t a_sw(uint32_t m, uint32_t u) {
    return m * 512u + ((((u ^ m) & 7u) | (u & 24u)) << 4);
}

#define LDSM4(r0, r1, r2, r3, addr) \
    asm volatile("ldmatrix.sync.aligned.m8n8.x4.shared.b16 {%0,%1,%2,%3}, [%4];" \
                 : "=r"(r0), "=r"(r1), "=r"(r2), "=r"(r3) : "r"(addr))

static __device__ __forceinline__ void mma16816(float* c, const uint32_t* a,
                                                uint32_t b0, uint32_t b1) {
    asm volatile("mma.sync.aligned.m16n8k16.row.col.f32.f16.f16.f32 "
                 "{%0,%1,%2,%3}, {%4,%5,%6,%7}, {%8,%9}, {%0,%1,%2,%3};"
                 : "+f"(c[0]), "+f"(c[1]), "+f"(c[2]), "+f"(c[3])
                 : "r"(a[0]), "r"(a[1]), "r"(a[2]), "r"(a[3]), "r"(b0), "r"(b1));
}

// MUFU-based sin
static __device__ __forceinline__ float fast_sin(float a) {
    return __sinf(a);
}

// ---------------- prep: pack W into MMA-fragment order ----------------
__global__ void prep_frag_kernel(const float* __restrict__ Wh) {
    const int t   = blockIdx.x * 256 + threadIdx.x;   // 0..16383 within mat
    const int mat = blockIdx.y;
    const int lane = t & 31;
    const int nt   = (t >> 5) & 3;
    const int h    = (t >> 7) & 1;
    const int c    = (t >> 8) & 7;
    const int sl   = t >> 11;
    const int n = sl * 32 + nt * 8 + (lane >> 2);
    const int k = c * 32 + h * 16 + (lane & 3) * 2;
    const float* src = Wh + (size_t)mat * 65536;      // [k][n]
    unsigned short a0 = __half_as_ushort(__float2half_rn(src[(k + 0) * 256 + n]));
    unsigned short a1 = __half_as_ushort(__float2half_rn(src[(k + 1) * 256 + n]));
    unsigned short a8 = __half_as_ushort(__float2half_rn(src[(k + 8) * 256 + n]));
    unsigned short a9 = __half_as_ushort(__float2half_rn(src[(k + 9) * 256 + n]));
    uint32_t b0 = (uint32_t)a0 | ((uint32_t)a1 << 16);
    uint32_t b1 = (uint32_t)a8 | ((uint32_t)a9 << 16);
    g_Wf[(size_t)mat * 16384 + t] = (u64)b0 | ((u64)b1 << 32);
}

__global__ void zero_out_kernel(float* __restrict__ out) {
    int i = blockIdx.x * 256 + threadIdx.x;
    if (i < NPTS * 3) out[i] = 0.f;
}

// ---------------- main kernel ----------------
extern __shared__ char smem[];

__global__ void __launch_bounds__(NTHR, 2)
moe_mma_kernel(const float* __restrict__ x,
               const float* __restrict__ gate_W,
               const float* __restrict__ gate_b,
               const float* __restrict__ W0,
               const float* __restrict__ b0,
               const float* __restrict__ Wh_unused,
               const float* __restrict__ bh,
               const float* __restrict__ Wout,
               const float* __restrict__ bout,
               float* __restrict__ out)
{
    const uint32_t smem0 = smem_u32(smem);
    char*  sc     = smem;
    float* wout_s = (float*)(sc + S_WOUT);
    float* w0s    = (float*)(sc + S_W0S);
    float* xs     = (float*)(sc + S_XS);
    float* red    = (float*)(sc + S_A1);     // alias (A1 dead in last layer)

    const int tile = blockIdx.x >> 1;        // point tile
    const int e0   = (blockIdx.x & 1) * EPG; // expert group start

    const int tid  = threadIdx.x;
    const int lane = tid & 31;
    const int wid  = tid >> 5;               // warp owns n-slice [wid*32, wid*32+32)
    const int nw   = wid * 32;
    const int m0l  = lane & 15;              // A ldmatrix row base

    if (tid < 128) xs[tid] = x[tile * 128 + tid];
    __syncthreads();

    // gate softmax (threads < 64 own one point) — all 8 logits for normalization
    float gts[EPG];
    float cb0 = 0.f, cb1 = 0.f, cb2 = 0.f;
    if (tid < TILE_M) {
        float x0 = xs[tid * 2], x1 = xs[tid * 2 + 1];
        float lg[E_EXP];
        float mx = -1e30f;
        #pragma unroll
        for (int e = 0; e < E_EXP; e++) {
            float v = fmaf(x0, __ldg(gate_W + e), fmaf(x1, __ldg(gate_W + 8 + e), __ldg(gate_b + e)));
            lg[e] = v; mx = fmaxf(mx, v);
        }
        float s = 0.f;
        #pragma unroll
        for (int e = 0; e < E_EXP; e++) { lg[e] = expf(lg[e] - mx); s += lg[e]; }
        float inv = 1.0f / s;
        #pragma unroll
        for (int q = 0; q < EPG; q++) gts[q] = lg[e0 + q] * inv;
    }

    #pragma unroll 1
    for (int eq = 0; eq < EPG; eq++) {
        const int e = e0 + eq;
        // stage Wout[e] -> [256][4]; W0/b0 -> w0s[768]
        wout_s[tid * 4 + 0] = __ldg(Wout + e * 768 + tid * 3 + 0);
        wout_s[tid * 4 + 1] = __ldg(Wout + e * 768 + tid * 3 + 1);
        wout_s[tid * 4 + 2] = __ldg(Wout + e * 768 + tid * 3 + 2);
        wout_s[tid * 4 + 3] = 0.f;
        for (int i = tid; i < 768; i += NTHR)
            w0s[i] = (i < 512) ? __ldg(W0 + e * 512 + i) : __ldg(b0 + e * 256 + (i - 512));
        __syncthreads();

        // -------- layer 0 (K=2, fp32) -> A (fp16) into A0 --------
        {
            const int m = tid >> 2, p = tid & 3;
            const float x0 = xs[m * 2], x1 = xs[m * 2 + 1];
            #pragma unroll 4
            for (int j = 0; j < 32; j++) {
                int c0 = j * 8 + p * 2;
                float z0 = fmaf(x0, w0s[c0],     fmaf(x1, w0s[256 + c0],     w0s[512 + c0]));
                float z1 = fmaf(x0, w0s[c0 + 1], fmaf(x1, w0s[256 + c0 + 1], w0s[512 + c0 + 1]));
                float s0 = fast_sin(OMEGA * z0);
                float s1 = fast_sin(OMEGA * z1);
                __half2 h = __floats2half2_rn(s0, s1);
                uint32_t off = a_sw(m, j) + p * 4;
                *(uint32_t*)(sc + S_A0 + off) = *(uint32_t*)&h;
            }
            __syncthreads();
        }

        // -------- hidden layers; A ping-pongs: l0 A0->A1, l1 A1->A0, l2 A0->red --------
        uint32_t aoff = 0;   // read offset for this layer
        #pragma unroll 1
        for (int l = 0; l < NHID; l++) {
            const float* bbg = bh + (e * 3 + l) * 256;
            const u64* wf = g_Wf + (size_t)(e * 3 + l) * 16384 + (wid << 11) + lane;

            float cacc[4][4][4];
            #pragma unroll
            for (int mt = 0; mt < 4; mt++)
                #pragma unroll
                for (int nt = 0; nt < 4; nt++)
                    #pragma unroll
                    for (int q = 0; q < 4; q++) cacc[mt][nt][q] = 0.f;

            // -------- register-direct W fragments, double-buffered one chunk ahead --------
            uint2 bfr[2][8];   // [buf][h*4+nt]
            #pragma unroll
            for (int q = 0; q < 8; q++)
                bfr[0][q] = __ldg((const uint2*)(wf + q * 32));

            #pragma unroll
            for (int c = 0; c < 8; c++) {
                const int cur = c & 1;
                if (c < 7) {
                    const u64* wn = wf + (c + 1) * 256;
                    #pragma unroll
                    for (int q = 0; q < 8; q++)
                        bfr[cur ^ 1][q] = __ldg((const uint2*)(wn + q * 32));
                }
                #pragma unroll
                for (int h = 0; h < 2; h++) {
                    const uint32_t ubase = (uint32_t)(c * 4 + h * 2) + (uint32_t)(lane >> 4);
                    uint32_t af[4][4];
                    #pragma unroll
                    for (int mt = 0; mt < 4; mt++) {
                        uint32_t aa = smem0 + S_A0 + aoff + a_sw((uint32_t)(mt * 16 + m0l), ubase);
                        LDSM4(af[mt][0], af[mt][1], af[mt][2], af[mt][3], aa);
                    }
                    #pragma unroll
                    for (int mt = 0; mt < 4; mt++)
                        #pragma unroll
                        for (int nt = 0; nt < 4; nt++)
                            mma16816(cacc[mt][nt], af[mt],
                                     bfr[cur][h * 4 + nt].x, bfr[cur][h * 4 + nt].y);
                }
            }

            // epilogue writes the OTHER A buffer (or red); bias via L2 __ldg
            if (l < NHID - 1) {
                const uint32_t dst = (uint32_t)S_A0 + (aoff ^ 32768u);
                #pragma unroll
                for (int mt = 0; mt < 4; mt++) {
                    int r0 = mt * 16 + (lane >> 2);
                    #pragma unroll
                    for (int nt = 0; nt < 4; nt++) {
                        int n0 = nw + nt * 8 + 2 * (lane & 3);
                        uint32_t u = (uint32_t)(n0 >> 3);
                        float2 bb = *(const float2*)(bbg + n0);
                        float* cc = cacc[mt][nt];
                        float s00 = fast_sin(OMEGA * (cc[0] + bb.x));
                        float s01 = fast_sin(OMEGA * (cc[1] + bb.y));
                        float s10 = fast_sin(OMEGA * (cc[2] + bb.x));
                        float s11 = fast_sin(OMEGA * (cc[3] + bb.y));
                        __half2 h0 = __floats2half2_rn(s00, s01);
                        __half2 h1 = __floats2half2_rn(s10, s11);
                        uint32_t o0 = a_sw((uint32_t)r0, u) + (lane & 3) * 4;
                        uint32_t o1 = a_sw((uint32_t)(r0 + 8), u) + (lane & 3) * 4;
                        *(uint32_t*)(sc + dst + o0) = *(uint32_t*)&h0;
                        *(uint32_t*)(sc + dst + o1) = *(uint32_t*)&h1;
                    }
                }
                aoff ^= 32768u;
                __syncthreads();   // next layer's A complete
            } else {
                // last layer: bias + sin + Wout dot + reduce + gated combine
                float o[8][3];
                #pragma unroll
                for (int i = 0; i < 8; i++)
                    #pragma unroll
                    for (int c3 = 0; c3 < 3; c3++) o[i][c3] = 0.f;
                #pragma unroll
                for (int mt = 0; mt < 4; mt++) {
                    #pragma unroll
                    for (int nt = 0; nt < 4; nt++) {
                        int n0 = nw + nt * 8 + 2 * (lane & 3);
                        float2 bb = *(const float2*)(bbg + n0);
                        float* cc = cacc[mt][nt];
                        float s00 = fast_sin(OMEGA * (cc[0] + bb.x));
                        float s01 = fast_sin(OMEGA * (cc[1] + bb.y));
                        float s10 = fast_sin(OMEGA * (cc[2] + bb.x));
                        float s11 = fast_sin(OMEGA * (cc[3] + bb.y));
                        const float* wA = wout_s + n0 * 4;
                        const float* wB = wout_s + (n0 + 1) * 4;
                        #pragma unroll
                        for (int c3 = 0; c3 < 3; c3++) {
                            o[mt * 2 + 0][c3] = fmaf(s00, wA[c3], fmaf(s01, wB[c3], o[mt * 2 + 0][c3]));
                            o[mt * 2 + 1][c3] = fmaf(s10, wA[c3], fmaf(s11, wB[c3], o[mt * 2 + 1][c3]));
                        }
                    }
                }
                #pragma unroll
                for (int i = 0; i < 8; i++)
                    #pragma unroll
                    for (int c3 = 0; c3 < 3; c3++) {
                        float v = o[i][c3];
                        v += __shfl_xor_sync(0xFFFFFFFF, v, 1);
                        v += __shfl_xor_sync(0xFFFFFFFF, v, 2);
                        o[i][c3] = v;
                    }
                if ((lane & 3) == 0) {
                    int q = lane >> 2;
                    #pragma unroll
                    for (int mt = 0; mt < 4; mt++)
                        #pragma unroll
                        for (int i = 0; i < 2; i++) {
                            int r = mt * 16 + i * 8 + q;
                            #pragma unroll
                            for (int c3 = 0; c3 < 3; c3++)
                                red[r * 24 + wid * 3 + c3] = o[mt * 2 + i][c3];
                        }
                }
                __syncthreads();   // all red written; all warps past K-loop
                if (tid < TILE_M) {
                    float g = gts[eq];
                    #pragma unroll
                    for (int c3 = 0; c3 < 3; c3++) {
                        float oc = __ldg(bout + e * 3 + c3);
                        #pragma unroll
                        for (int w = 0; w < 8; w++)
                            oc += red[tid * 24 + w * 3 + c3];
                        if (c3 == 0) cb0 = fmaf(g, oc, cb0);
                        else if (c3 == 1) cb1 = fmaf(g, oc, cb1);
                        else cb2 = fmaf(g, oc, cb2);
                    }
                }
                __syncthreads();   // red consumed before next expert's layer 0
            }
        }
    }

    if (tid < TILE_M) {
        int r = tile * TILE_M + tid;
        atomicAdd(&out[r * 3 + 0], cb0);
        atomicAdd(&out[r * 3 + 1], cb1);
        atomicAdd(&out[r * 3 + 2], cb2);
    }
}

extern "C" void kernel_launch(void* const* d_in, const int* in_sizes, int n_in,
                              void* d_out, int out_size) {
    (void)in_sizes; (void)n_in; (void)out_size;
    const float* x      = (const float*)d_in[0];
    const float* gate_W = (const float*)d_in[1];
    const float* gate_b = (const float*)d_in[2];
    const float* W0     = (const float*)d_in[3];
    const float* b0     = (const float*)d_in[4];
    const float* Wh     = (const float*)d_in[5];
    const float* bh     = (const float*)d_in[6];
    const float* Wout   = (const float*)d_in[7];
    const float* bout   = (const float*)d_in[8];
    float* out = (float*)d_out;

    dim3 pg(64, NMAT);
    prep_frag_kernel<<<pg, 256>>>(Wh);
    zero_out_kernel<<<(NPTS * 3 + 255) / 256, 256>>>(out);

    cudaFuncSetAttribute(moe_mma_kernel,
                         cudaFuncAttributeMaxDynamicSharedMemorySize, SMEM_BYTES);
    moe_mma_kernel<<<(NPTS / TILE_M) * NGRP, NTHR, SMEM_BYTES>>>(
        x, gate_W, gate_b, W0, b0, Wh, bh, Wout, bout, out);
}